// round 9
// baseline (speedup 1.0000x reference)
#include <cuda_runtime.h>

// Problem constants
#define T_SEQ  2048
#define HEADK  512
#define NHEAD  8
#define NBATCH 4
#define MTOT   (NBATCH * T_SEQ)   // 8192
#define DMOD   (NHEAD * HEADK)    // 4096

// Scratch (static __device__ globals — allocation-free per harness rules)
__device__ float g_Q[MTOT * DMOD];                       // 128 MB
__device__ float g_K[MTOT * DMOD];                       // 128 MB
__device__ float g_V[MTOT * DMOD];                       // 128 MB
__device__ float g_O[MTOT * DMOD];                       // 128 MB
__device__ float g_S[NBATCH * NHEAD * T_SEQ * T_SEQ];    // 512 MB

__device__ __forceinline__ unsigned f2tf(float x) {
    unsigned u;
    asm("cvt.rna.tf32.f32 %0, %1;" : "=r"(u) : "f"(x));
    return u;
}

__device__ __forceinline__ void mma_tf32(float* d, const unsigned* a, const unsigned* b) {
    asm volatile(
        "mma.sync.aligned.m16n8k8.row.col.f32.tf32.tf32.f32 "
        "{%0,%1,%2,%3},{%4,%5,%6,%7},{%8,%9},{%0,%1,%2,%3};\n"
        : "+f"(d[0]), "+f"(d[1]), "+f"(d[2]), "+f"(d[3])
        : "r"(a[0]), "r"(a[1]), "r"(a[2]), "r"(a[3]), "r"(b[0]), "r"(b[1]));
}

// Generic batched tf32 GEMM.
//   C[m][n] = alpha * sum_k A[m][k] * Bl[k][n] (+ bias[n])
//   NT=false: Bl[k][n] = B[k*ldb + n]   (B row-major [K,N])
//   NT=true : Bl[k][n] = B[n*ldb + k]   (B row-major [N,K], used transposed)
// Batch z: offsets = (z/nh)*s?b + (z%nh)*s?h for A, B, C.
// All of M, N divisible by 128; Kd divisible by 16 (true for every call here).
template <bool NT, bool HASBIAS>
__global__ void __launch_bounds__(256, 2)
gemm_tf32_kernel(const float* __restrict__ A, const float* __restrict__ B,
                 float* __restrict__ C, const float* __restrict__ bias,
                 int lda, int ldb, int ldc, int Kd, float alpha, int nh,
                 long long sAb, long long sAh,
                 long long sBb, long long sBh,
                 long long sCb, long long sCh)
{
    constexpr int BM = 128, BN = 128, BK = 16;
    constexpr int AST = BK + 4;   // 20 floats/row: conflict-free A-frag LDS
    constexpr int BST = BN + 8;   // 136 floats/row: conflict-free B-frag LDS
    __shared__ __align__(16) float As[2][BM * AST];
    __shared__ __align__(16) float Bs[2][BK * BST];

    const int tid  = threadIdx.x;
    const int lane = tid & 31;
    const int wid  = tid >> 5;
    const int wm   = (wid & 1) * 64;    // warp tile 64x32
    const int wn   = (wid >> 1) * 32;
    const int gq   = lane >> 2;         // groupID
    const int qt   = lane & 3;          // threadID in group

    const int z  = blockIdx.z;
    const int bb = z / nh;
    const int hh = z - bb * nh;
    A += bb * sAb + hh * sAh;
    B += bb * sBb + hh * sBh;
    C += bb * sCb + hh * sCh;

    const int row0 = blockIdx.y * BM;
    const int col0 = blockIdx.x * BN;

    const float* Ag = A + (long long)row0 * lda;
    const float* Bg = NT ? (B + (long long)col0 * ldb) : (B + col0);

    float4 ra[2], rb[2];

    auto ldA = [&](int kt) {
        const float* p = Ag + kt * BK;
#pragma unroll
        for (int i = 0; i < 2; i++) {
            int s = tid + i * 256, r = s >> 2, c = (s & 3) << 2;
            ra[i] = *reinterpret_cast<const float4*>(p + (long long)r * lda + c);
        }
    };
    auto ldB = [&](int kt) {
        if (NT) {
            const float* p = Bg + kt * BK;
#pragma unroll
            for (int i = 0; i < 2; i++) {
                int s = tid + i * 256, n = s >> 2, c = (s & 3) << 2;
                rb[i] = *reinterpret_cast<const float4*>(p + (long long)n * ldb + c);
            }
        } else {
            const float* p = Bg + (long long)(kt * BK) * ldb;
#pragma unroll
            for (int i = 0; i < 2; i++) {
                int s = tid + i * 256, r = s >> 5, c = (s & 31) << 2;
                rb[i] = *reinterpret_cast<const float4*>(p + (long long)r * ldb + c);
            }
        }
    };
    auto stA = [&](int buf) {
#pragma unroll
        for (int i = 0; i < 2; i++) {
            int s = tid + i * 256, r = s >> 2, c = (s & 3) << 2;
            uint4 u = make_uint4(f2tf(ra[i].x), f2tf(ra[i].y), f2tf(ra[i].z), f2tf(ra[i].w));
            *reinterpret_cast<uint4*>(&As[buf][r * AST + c]) = u;
        }
    };
    auto stB = [&](int buf) {
        if (NT) {
#pragma unroll
            for (int i = 0; i < 2; i++) {
                int s = tid + i * 256, n = s >> 2, c = (s & 3) << 2;
                float v[4] = {rb[i].x, rb[i].y, rb[i].z, rb[i].w};
#pragma unroll
                for (int j = 0; j < 4; j++)
                    Bs[buf][(c + j) * BST + n] = __uint_as_float(f2tf(v[j]));
            }
        } else {
#pragma unroll
            for (int i = 0; i < 2; i++) {
                int s = tid + i * 256, r = s >> 5, c = (s & 31) << 2;
                uint4 u = make_uint4(f2tf(rb[i].x), f2tf(rb[i].y), f2tf(rb[i].z), f2tf(rb[i].w));
                *reinterpret_cast<uint4*>(&Bs[buf][r * BST + c]) = u;
            }
        }
    };

    float acc[4][4][4];
#pragma unroll
    for (int i = 0; i < 4; i++)
#pragma unroll
        for (int j = 0; j < 4; j++)
#pragma unroll
            for (int r = 0; r < 4; r++) acc[i][j][r] = 0.f;

    const int nk = Kd / BK;
    ldA(0); ldB(0);
    stA(0); stB(0);
    __syncthreads();

    for (int kt = 0; kt < nk; ++kt) {
        const int cur = kt & 1;
        if (kt + 1 < nk) { ldA(kt + 1); ldB(kt + 1); }

        const unsigned* Au = reinterpret_cast<const unsigned*>(As[cur]);
        const unsigned* Bu = reinterpret_cast<const unsigned*>(Bs[cur]);
#pragma unroll
        for (int ks = 0; ks < BK; ks += 8) {
            unsigned af[4][4], bf[4][2];
#pragma unroll
            for (int mi = 0; mi < 4; mi++) {
                int r = wm + mi * 16;
                af[mi][0] = Au[(r + gq)     * AST + ks + qt];
                af[mi][1] = Au[(r + gq + 8) * AST + ks + qt];
                af[mi][2] = Au[(r + gq)     * AST + ks + qt + 4];
                af[mi][3] = Au[(r + gq + 8) * AST + ks + qt + 4];
            }
#pragma unroll
            for (int nj = 0; nj < 4; nj++) {
                int c = wn + nj * 8 + gq;
                bf[nj][0] = Bu[(ks + qt)     * BST + c];
                bf[nj][1] = Bu[(ks + qt + 4) * BST + c];
            }
#pragma unroll
            for (int mi = 0; mi < 4; mi++)
#pragma unroll
                for (int nj = 0; nj < 4; nj++)
                    mma_tf32(acc[mi][nj], af[mi], bf[nj]);
        }

        if (kt + 1 < nk) { stA((kt + 1) & 1); stB((kt + 1) & 1); }
        __syncthreads();
    }

    // Epilogue: C = alpha*acc (+ bias)
#pragma unroll
    for (int mi = 0; mi < 4; mi++) {
#pragma unroll
        for (int nj = 0; nj < 4; nj++) {
            int r = row0 + wm + mi * 16 + gq;
            int c = col0 + wn + nj * 8 + qt * 2;
            float b0 = 0.f, b1 = 0.f;
            if (HASBIAS) { b0 = bias[c]; b1 = bias[c + 1]; }
            float2 v0 = make_float2(acc[mi][nj][0] * alpha + b0,
                                    acc[mi][nj][1] * alpha + b1);
            float2 v1 = make_float2(acc[mi][nj][2] * alpha + b0,
                                    acc[mi][nj][3] * alpha + b1);
            *reinterpret_cast<float2*>(&C[(long long)r * ldc + c])       = v0;
            *reinterpret_cast<float2*>(&C[(long long)(r + 8) * ldc + c]) = v1;
        }
    }
}

// One block per row of 2048; single global read + write.
__global__ void __launch_bounds__(256)
softmax2048(float* __restrict__ S)
{
    __shared__ float red[8];
    const long long row = blockIdx.x;
    float4* p4 = reinterpret_cast<float4*>(S + row * 2048);
    const int t = threadIdx.x, lane = t & 31, wid = t >> 5;

    float4 v0 = p4[t];
    float4 v1 = p4[t + 256];

    float m = fmaxf(fmaxf(fmaxf(v0.x, v0.y), fmaxf(v0.z, v0.w)),
                    fmaxf(fmaxf(v1.x, v1.y), fmaxf(v1.z, v1.w)));
#pragma unroll
    for (int o = 16; o; o >>= 1) m = fmaxf(m, __shfl_xor_sync(0xffffffffu, m, o));
    if (lane == 0) red[wid] = m;
    __syncthreads();
    float mm = red[0];
#pragma unroll
    for (int i = 1; i < 8; i++) mm = fmaxf(mm, red[i]);
    __syncthreads();

    v0.x = expf(v0.x - mm); v0.y = expf(v0.y - mm);
    v0.z = expf(v0.z - mm); v0.w = expf(v0.w - mm);
    v1.x = expf(v1.x - mm); v1.y = expf(v1.y - mm);
    v1.z = expf(v1.z - mm); v1.w = expf(v1.w - mm);

    float s = (v0.x + v0.y) + (v0.z + v0.w) + (v1.x + v1.y) + (v1.z + v1.w);
#pragma unroll
    for (int o = 16; o; o >>= 1) s += __shfl_xor_sync(0xffffffffu, s, o);
    if (lane == 0) red[wid] = s;
    __syncthreads();
    float ss = ((red[0] + red[1]) + (red[2] + red[3])) +
               ((red[4] + red[5]) + (red[6] + red[7]));
    float inv = 1.0f / ss;

    v0.x *= inv; v0.y *= inv; v0.z *= inv; v0.w *= inv;
    v1.x *= inv; v1.y *= inv; v1.z *= inv; v1.w *= inv;
    p4[t]       = v0;
    p4[t + 256] = v1;
}

extern "C" void kernel_launch(void* const* d_in, const int* in_sizes, int n_in,
                              void* d_out, int out_size)
{
    (void)in_sizes; (void)n_in; (void)out_size;
    const float* x  = (const float*)d_in[0];
    const float* Wq = (const float*)d_in[1];
    const float* Wk = (const float*)d_in[2];
    const float* Wv = (const float*)d_in[3];
    const float* Wu = (const float*)d_in[4];
    const float* bu = (const float*)d_in[5];
    float* out = (float*)d_out;

    float *Q, *K, *V, *O, *S;
    cudaGetSymbolAddress((void**)&Q, g_Q);
    cudaGetSymbolAddress((void**)&K, g_K);
    cudaGetSymbolAddress((void**)&V, g_V);
    cudaGetSymbolAddress((void**)&O, g_O);
    cudaGetSymbolAddress((void**)&S, g_S);

    const dim3 blk(256);
    const long long sQKVh = HEADK;                            // head offset in Q/K/V/O rows
    const long long sQKVb = (long long)T_SEQ * DMOD;          // batch offset in Q/K/V/O
    const long long sSb   = (long long)NHEAD * T_SEQ * T_SEQ; // batch offset in S
    const long long sSh   = (long long)T_SEQ * T_SEQ;         // head offset in S

    // 1) QKV projections: [8192,512] @ [512,4096]
    gemm_tf32_kernel<false, false><<<dim3(DMOD / 128, MTOT / 128, 1), blk>>>(
        x, Wq, Q, nullptr, HEADK, DMOD, DMOD, HEADK, 1.f, 1, 0, 0, 0, 0, 0, 0);
    gemm_tf32_kernel<false, false><<<dim3(DMOD / 128, MTOT / 128, 1), blk>>>(
        x, Wk, K, nullptr, HEADK, DMOD, DMOD, HEADK, 1.f, 1, 0, 0, 0, 0, 0, 0);
    gemm_tf32_kernel<false, false><<<dim3(DMOD / 128, MTOT / 128, 1), blk>>>(
        x, Wv, V, nullptr, HEADK, DMOD, DMOD, HEADK, 1.f, 1, 0, 0, 0, 0, 0, 0);

    // 2) scores: S[b,h] = (1/sqrt(K)) * Q_bh @ K_bh^T   (NT), per (b,h)
    gemm_tf32_kernel<true, false><<<dim3(T_SEQ / 128, T_SEQ / 128, NBATCH * NHEAD), blk>>>(
        Q, K, S, nullptr, DMOD, DMOD, T_SEQ, HEADK,
        0.04419417382415922f /* 512^-0.5 */, NHEAD,
        sQKVb, sQKVh, sQKVb, sQKVh, sSb, sSh);

    // 3) softmax over last dim (2048), one block per row
    softmax2048<<<NBATCH * NHEAD * T_SEQ, 256>>>(S);

    // 4) O[b,h] = P_bh @ V_bh, written directly into [b, t, h*K] layout
    gemm_tf32_kernel<false, false><<<dim3(HEADK / 128, T_SEQ / 128, NBATCH * NHEAD), blk>>>(
        S, V, O, nullptr, T_SEQ, DMOD, DMOD, T_SEQ, 1.f, NHEAD,
        sSb, sSh, sQKVb, sQKVh, sQKVb, sQKVh);

    // 5) final: out = O @ Wu + bu   ([8192,4096] @ [4096,512])
    gemm_tf32_kernel<false, true><<<dim3(512 / 128, MTOT / 128, 1), blk>>>(
        O, Wu, out, bu, DMOD, 512, 512, DMOD, 1.f, 1, 0, 0, 0, 0, 0, 0);
}

// round 10
// speedup vs baseline: 1.0016x; 1.0016x over previous
#include <cuda_runtime.h>

// Problem constants
#define T_SEQ  2048
#define HEADK  512
#define NHEAD  8
#define NBATCH 4
#define MTOT   (NBATCH * T_SEQ)   // 8192
#define DMOD   (NHEAD * HEADK)    // 4096

// Scratch (static __device__ globals — allocation-free per harness rules)
__device__ float g_Q[MTOT * DMOD];                       // 128 MB
__device__ float g_K[MTOT * DMOD];                       // 128 MB
__device__ float g_V[MTOT * DMOD];                       // 128 MB
__device__ float g_O[MTOT * DMOD];                       // 128 MB
__device__ float g_S[NBATCH * NHEAD * T_SEQ * T_SEQ];    // 512 MB

__device__ __forceinline__ unsigned f2tf(float x) {
    unsigned u;
    asm("cvt.rna.tf32.f32 %0, %1;" : "=r"(u) : "f"(x));
    return u;
}

__device__ __forceinline__ void mma_tf32(float* d, const unsigned* a, const unsigned* b) {
    asm volatile(
        "mma.sync.aligned.m16n8k8.row.col.f32.tf32.tf32.f32 "
        "{%0,%1,%2,%3},{%4,%5,%6,%7},{%8,%9},{%0,%1,%2,%3};\n"
        : "+f"(d[0]), "+f"(d[1]), "+f"(d[2]), "+f"(d[3])
        : "r"(a[0]), "r"(a[1]), "r"(a[2]), "r"(a[3]), "r"(b[0]), "r"(b[1]));
}

// Generic batched tf32 GEMM.
//   C[m][n] = alpha * sum_k A[m][k] * Bl[k][n] (+ bias[n])
//   NT=false: Bl[k][n] = B[k*ldb + n]   (B row-major [K,N])
//   NT=true : Bl[k][n] = B[n*ldb + k]   (B row-major [N,K], used transposed)
// Batch z: offsets = (z/nh)*s?b + (z%nh)*s?h for A, B, C.
// All of M, N divisible by 128; Kd divisible by 16 (true for every call here).
template <bool NT, bool HASBIAS>
__global__ void __launch_bounds__(256, 2)
gemm_tf32_kernel(const float* __restrict__ A, const float* __restrict__ B,
                 float* __restrict__ C, const float* __restrict__ bias,
                 int lda, int ldb, int ldc, int Kd, float alpha, int nh,
                 long long sAb, long long sAh,
                 long long sBb, long long sBh,
                 long long sCb, long long sCh)
{
    constexpr int BM = 128, BN = 128, BK = 16;
    constexpr int AST = BK + 4;   // 20 floats/row: conflict-free A-frag LDS
    constexpr int BST = BN + 8;   // 136 floats/row: conflict-free B-frag LDS
    __shared__ __align__(16) float As[2][BM * AST];
    __shared__ __align__(16) float Bs[2][BK * BST];

    const int tid  = threadIdx.x;
    const int lane = tid & 31;
    const int wid  = tid >> 5;
    const int wm   = (wid & 1) * 64;    // warp tile 64x32
    const int wn   = (wid >> 1) * 32;
    const int gq   = lane >> 2;         // groupID
    const int qt   = lane & 3;          // threadID in group

    const int z  = blockIdx.z;
    const int bb = z / nh;
    const int hh = z - bb * nh;
    A += bb * sAb + hh * sAh;
    B += bb * sBb + hh * sBh;
    C += bb * sCb + hh * sCh;

    const int row0 = blockIdx.y * BM;
    const int col0 = blockIdx.x * BN;

    const float* Ag = A + (long long)row0 * lda;
    const float* Bg = NT ? (B + (long long)col0 * ldb) : (B + col0);

    float4 ra[2], rb[2];

    auto ldA = [&](int kt) {
        const float* p = Ag + kt * BK;
#pragma unroll
        for (int i = 0; i < 2; i++) {
            int s = tid + i * 256, r = s >> 2, c = (s & 3) << 2;
            ra[i] = *reinterpret_cast<const float4*>(p + (long long)r * lda + c);
        }
    };
    auto ldB = [&](int kt) {
        if (NT) {
            const float* p = Bg + kt * BK;
#pragma unroll
            for (int i = 0; i < 2; i++) {
                int s = tid + i * 256, n = s >> 2, c = (s & 3) << 2;
                rb[i] = *reinterpret_cast<const float4*>(p + (long long)n * ldb + c);
            }
        } else {
            const float* p = Bg + (long long)(kt * BK) * ldb;
#pragma unroll
            for (int i = 0; i < 2; i++) {
                int s = tid + i * 256, r = s >> 5, c = (s & 31) << 2;
                rb[i] = *reinterpret_cast<const float4*>(p + (long long)r * ldb + c);
            }
        }
    };
    auto stA = [&](int buf) {
#pragma unroll
        for (int i = 0; i < 2; i++) {
            int s = tid + i * 256, r = s >> 2, c = (s & 3) << 2;
            uint4 u = make_uint4(f2tf(ra[i].x), f2tf(ra[i].y), f2tf(ra[i].z), f2tf(ra[i].w));
            *reinterpret_cast<uint4*>(&As[buf][r * AST + c]) = u;
        }
    };
    auto stB = [&](int buf) {
        if (NT) {
#pragma unroll
            for (int i = 0; i < 2; i++) {
                int s = tid + i * 256, n = s >> 2, c = (s & 3) << 2;
                float v[4] = {rb[i].x, rb[i].y, rb[i].z, rb[i].w};
#pragma unroll
                for (int j = 0; j < 4; j++)
                    Bs[buf][(c + j) * BST + n] = __uint_as_float(f2tf(v[j]));
            }
        } else {
#pragma unroll
            for (int i = 0; i < 2; i++) {
                int s = tid + i * 256, r = s >> 5, c = (s & 31) << 2;
                uint4 u = make_uint4(f2tf(rb[i].x), f2tf(rb[i].y), f2tf(rb[i].z), f2tf(rb[i].w));
                *reinterpret_cast<uint4*>(&Bs[buf][r * BST + c]) = u;
            }
        }
    };

    float acc[4][4][4];
#pragma unroll
    for (int i = 0; i < 4; i++)
#pragma unroll
        for (int j = 0; j < 4; j++)
#pragma unroll
            for (int r = 0; r < 4; r++) acc[i][j][r] = 0.f;

    const int nk = Kd / BK;
    ldA(0); ldB(0);
    stA(0); stB(0);
    __syncthreads();

    for (int kt = 0; kt < nk; ++kt) {
        const int cur = kt & 1;
        if (kt + 1 < nk) { ldA(kt + 1); ldB(kt + 1); }

        const unsigned* Au = reinterpret_cast<const unsigned*>(As[cur]);
        const unsigned* Bu = reinterpret_cast<const unsigned*>(Bs[cur]);
#pragma unroll
        for (int ks = 0; ks < BK; ks += 8) {
            unsigned af[4][4], bf[4][2];
#pragma unroll
            for (int mi = 0; mi < 4; mi++) {
                int r = wm + mi * 16;
                af[mi][0] = Au[(r + gq)     * AST + ks + qt];
                af[mi][1] = Au[(r + gq + 8) * AST + ks + qt];
                af[mi][2] = Au[(r + gq)     * AST + ks + qt + 4];
                af[mi][3] = Au[(r + gq + 8) * AST + ks + qt + 4];
            }
#pragma unroll
            for (int nj = 0; nj < 4; nj++) {
                int c = wn + nj * 8 + gq;
                bf[nj][0] = Bu[(ks + qt)     * BST + c];
                bf[nj][1] = Bu[(ks + qt + 4) * BST + c];
            }
#pragma unroll
            for (int mi = 0; mi < 4; mi++)
#pragma unroll
                for (int nj = 0; nj < 4; nj++)
                    mma_tf32(acc[mi][nj], af[mi], bf[nj]);
        }

        if (kt + 1 < nk) { stA((kt + 1) & 1); stB((kt + 1) & 1); }
        __syncthreads();
    }

    // Epilogue: C = alpha*acc (+ bias)
#pragma unroll
    for (int mi = 0; mi < 4; mi++) {
#pragma unroll
        for (int nj = 0; nj < 4; nj++) {
            int r = row0 + wm + mi * 16 + gq;
            int c = col0 + wn + nj * 8 + qt * 2;
            float b0 = 0.f, b1 = 0.f;
            if (HASBIAS) { b0 = bias[c]; b1 = bias[c + 1]; }
            float2 v0 = make_float2(acc[mi][nj][0] * alpha + b0,
                                    acc[mi][nj][1] * alpha + b1);
            float2 v1 = make_float2(acc[mi][nj][2] * alpha + b0,
                                    acc[mi][nj][3] * alpha + b1);
            *reinterpret_cast<float2*>(&C[(long long)r * ldc + c])       = v0;
            *reinterpret_cast<float2*>(&C[(long long)(r + 8) * ldc + c]) = v1;
        }
    }
}

// One block per row of 2048; single global read + write.
__global__ void __launch_bounds__(256)
softmax2048(float* __restrict__ S)
{
    __shared__ float red[8];
    const long long row = blockIdx.x;
    float4* p4 = reinterpret_cast<float4*>(S + row * 2048);
    const int t = threadIdx.x, lane = t & 31, wid = t >> 5;

    float4 v0 = p4[t];
    float4 v1 = p4[t + 256];

    float m = fmaxf(fmaxf(fmaxf(v0.x, v0.y), fmaxf(v0.z, v0.w)),
                    fmaxf(fmaxf(v1.x, v1.y), fmaxf(v1.z, v1.w)));
#pragma unroll
    for (int o = 16; o; o >>= 1) m = fmaxf(m, __shfl_xor_sync(0xffffffffu, m, o));
    if (lane == 0) red[wid] = m;
    __syncthreads();
    float mm = red[0];
#pragma unroll
    for (int i = 1; i < 8; i++) mm = fmaxf(mm, red[i]);
    __syncthreads();

    v0.x = expf(v0.x - mm); v0.y = expf(v0.y - mm);
    v0.z = expf(v0.z - mm); v0.w = expf(v0.w - mm);
    v1.x = expf(v1.x - mm); v1.y = expf(v1.y - mm);
    v1.z = expf(v1.z - mm); v1.w = expf(v1.w - mm);

    float s = (v0.x + v0.y) + (v0.z + v0.w) + (v1.x + v1.y) + (v1.z + v1.w);
#pragma unroll
    for (int o = 16; o; o >>= 1) s += __shfl_xor_sync(0xffffffffu, s, o);
    if (lane == 0) red[wid] = s;
    __syncthreads();
    float ss = ((red[0] + red[1]) + (red[2] + red[3])) +
               ((red[4] + red[5]) + (red[6] + red[7]));
    float inv = 1.0f / ss;

    v0.x *= inv; v0.y *= inv; v0.z *= inv; v0.w *= inv;
    v1.x *= inv; v1.y *= inv; v1.z *= inv; v1.w *= inv;
    p4[t]       = v0;
    p4[t + 256] = v1;
}

extern "C" void kernel_launch(void* const* d_in, const int* in_sizes, int n_in,
                              void* d_out, int out_size)
{
    (void)in_sizes; (void)n_in; (void)out_size;
    const float* x  = (const float*)d_in[0];
    const float* Wq = (const float*)d_in[1];
    const float* Wk = (const float*)d_in[2];
    const float* Wv = (const float*)d_in[3];
    const float* Wu = (const float*)d_in[4];
    const float* bu = (const float*)d_in[5];
    float* out = (float*)d_out;

    float *Q, *K, *V, *O, *S;
    cudaGetSymbolAddress((void**)&Q, g_Q);
    cudaGetSymbolAddress((void**)&K, g_K);
    cudaGetSymbolAddress((void**)&V, g_V);
    cudaGetSymbolAddress((void**)&O, g_O);
    cudaGetSymbolAddress((void**)&S, g_S);

    const dim3 blk(256);
    const long long sQKVh = HEADK;                            // head offset in Q/K/V/O rows
    const long long sQKVb = (long long)T_SEQ * DMOD;          // batch offset in Q/K/V/O
    const long long sSb   = (long long)NHEAD * T_SEQ * T_SEQ; // batch offset in S
    const long long sSh   = (long long)T_SEQ * T_SEQ;         // head offset in S

    // 1) QKV projections: [8192,512] @ [512,4096]
    gemm_tf32_kernel<false, false><<<dim3(DMOD / 128, MTOT / 128, 1), blk>>>(
        x, Wq, Q, nullptr, HEADK, DMOD, DMOD, HEADK, 1.f, 1, 0, 0, 0, 0, 0, 0);
    gemm_tf32_kernel<false, false><<<dim3(DMOD / 128, MTOT / 128, 1), blk>>>(
        x, Wk, K, nullptr, HEADK, DMOD, DMOD, HEADK, 1.f, 1, 0, 0, 0, 0, 0, 0);
    gemm_tf32_kernel<false, false><<<dim3(DMOD / 128, MTOT / 128, 1), blk>>>(
        x, Wv, V, nullptr, HEADK, DMOD, DMOD, HEADK, 1.f, 1, 0, 0, 0, 0, 0, 0);

    // 2) scores: S[b,h] = (1/sqrt(K)) * Q_bh @ K_bh^T   (NT), per (b,h)
    gemm_tf32_kernel<true, false><<<dim3(T_SEQ / 128, T_SEQ / 128, NBATCH * NHEAD), blk>>>(
        Q, K, S, nullptr, DMOD, DMOD, T_SEQ, HEADK,
        0.04419417382415922f /* 512^-0.5 */, NHEAD,
        sQKVb, sQKVh, sQKVb, sQKVh, sSb, sSh);

    // 3) softmax over last dim (2048), one block per row
    softmax2048<<<NBATCH * NHEAD * T_SEQ, 256>>>(S);

    // 4) O[b,h] = P_bh @ V_bh, written directly into [b, t, h*K] layout
    gemm_tf32_kernel<false, false><<<dim3(HEADK / 128, T_SEQ / 128, NBATCH * NHEAD), blk>>>(
        S, V, O, nullptr, T_SEQ, DMOD, DMOD, T_SEQ, 1.f, NHEAD,
        sSb, sSh, sQKVb, sQKVh, sQKVb, sQKVh);

    // 5) final: out = O @ Wu + bu   ([8192,4096] @ [4096,512])
    gemm_tf32_kernel<false, true><<<dim3(512 / 128, MTOT / 128, 1), blk>>>(
        O, Wu, out, bu, DMOD, 512, 512, DMOD, 1.f, 1, 0, 0, 0, 0, 0, 0);
}